// round 3
// baseline (speedup 1.0000x reference)
#include <cuda_runtime.h>
#include <math_constants.h>

// Problem constants
#define HH 512
#define WW 512
#define NIMG 24          // 8 * 3 image slices per tensor
#define NBINS 362        // max integer radius 361 (+1)
#define NPIX (HH * WW)   // 262144 = 1<<18

// ---------------------------------------------------------------------------
// Scratch (static __device__ — no allocation)
// [0] = pred row-FFT, [1] = target row-FFT, each [img][y*512 + x]
__device__ float2 g_fft[2][NIMG][NPIX];
__device__ float  g_Smag[NIMG][NBINS];
__device__ float  g_Sd[NIMG][NBINS];

// ---------------------------------------------------------------------------
// Warp-synchronous 512-pt radix-2 DIT FFT. buf holds bit-reversed input.
// One warp owns the whole 512-element buffer; 256 butterflies/stage = 8/lane.
// tw[m] = exp(-2*pi*i*m/512), m in [0,256)
__device__ __forceinline__ void fft512(float2* buf, int lane, const float2* tw) {
#pragma unroll
    for (int s = 1; s <= 9; s++) {
        const int half = 1 << (s - 1);
#pragma unroll
        for (int k = 0; k < 8; k++) {
            int t  = lane + (k << 5);
            int j  = t & (half - 1);
            int i0 = ((t >> (s - 1)) << s) + j;
            int i1 = i0 + half;
            float2 W = tw[j << (9 - s)];
            float2 u = buf[i0];
            float2 v = buf[i1];
            float2 vw = make_float2(v.x * W.x - v.y * W.y,
                                    v.x * W.y + v.y * W.x);
            buf[i0] = make_float2(u.x + vw.x, u.y + vw.y);
            buf[i1] = make_float2(u.x - vw.x, u.y - vw.y);
        }
        __syncwarp();
    }
}

__device__ __forceinline__ int rev9(int x) {
    return (int)(__brev((unsigned)x) >> 23);
}

// ---------------------------------------------------------------------------
// Zero the bin accumulators
__global__ void kzero() {
    int i = blockIdx.x * blockDim.x + threadIdx.x;
    if (i < NIMG * NBINS) {
        ((float*)g_Smag)[i] = 0.0f;
        ((float*)g_Sd)[i]   = 0.0f;
    }
}

// ---------------------------------------------------------------------------
// Pass 1: row FFTs of real input. 8 rows per block (1 warp per row).
// grid.x = 48 slices * 64 row-groups = 3072
__global__ void __launch_bounds__(256) kfft_rows(const float* __restrict__ pred,
                                                 const float* __restrict__ tgt) {
    __shared__ float2 buf[8][HH];
    __shared__ float2 tw[256];

    int tid = threadIdx.x;
    {   // build twiddle table (all 256 threads)
        float sn, cs;
        sincospif(-(float)tid / 256.0f, &sn, &cs);
        tw[tid] = make_float2(cs, sn);
    }

    int bid   = blockIdx.x;
    int slice = bid >> 6;          // 0..47
    int rg    = bid & 63;          // row group
    int tens  = (slice < NIMG) ? 0 : 1;
    int img   = (tens == 0) ? slice : slice - NIMG;
    const float* src = (tens == 0) ? pred : tgt;

    int w = tid >> 5, l = tid & 31;
    int y = rg * 8 + w;
    const float* row = src + ((size_t)img << 18) + ((size_t)y << 9);

#pragma unroll
    for (int k = 0; k < 16; k++) {
        int x = l + (k << 5);
        buf[w][rev9(x)] = make_float2(row[x], 0.0f);
    }
    __syncthreads();   // tw visible to all warps

    fft512(&buf[w][0], l, tw);

    float2* dst = g_fft[tens][img] + ((size_t)y << 9);
#pragma unroll
    for (int k = 0; k < 16; k++) {
        int x = l + (k << 5);
        dst[x] = buf[w][x];
    }
}

// ---------------------------------------------------------------------------
// Pass 2: column FFTs (pred + target together), per-pixel d/mag, bin sums.
// 8 columns per block (1 warp per column for both tensors).
// grid.x = 24 imgs * 64 col-groups = 1536, dynamic smem ~70 KB.
__global__ void __launch_bounds__(256) kfft_cols() {
    extern __shared__ unsigned char smem_raw[];
    float2* sP  = (float2*)smem_raw;           // 8*512
    float2* sT  = sP + 8 * HH;                 // 8*512
    float2* tw  = sT + 8 * HH;                 // 256
    float*  sbm = (float*)(tw + 256);          // NBINS
    float*  sbd = sbm + NBINS;                 // NBINS

    int tid = threadIdx.x;
    {
        float sn, cs;
        sincospif(-(float)tid / 256.0f, &sn, &cs);
        tw[tid] = make_float2(cs, sn);
    }
    for (int i = tid; i < NBINS; i += 256) { sbm[i] = 0.0f; sbd[i] = 0.0f; }

    int bid = blockIdx.x;
    int img = bid >> 6;
    int c0  = (bid & 63) << 3;

    const float2* srcP = g_fft[0][img];
    const float2* srcT = g_fft[1][img];

    // load 512x8 tile (both tensors), bit-reversed along y, transposed in smem
    for (int i = tid; i < 8 * HH; i += 256) {
        int cx = i & 7, y = i >> 3;
        int r  = rev9(y);
        float2 vP = srcP[((size_t)y << 9) + c0 + cx];
        float2 vT = srcT[((size_t)y << 9) + c0 + cx];
        sP[(cx << 9) + r] = vP;
        sT[(cx << 9) + r] = vT;
    }
    __syncthreads();

    int w = tid >> 5, l = tid & 31;
    fft512(sP + (w << 9), l, tw);
    fft512(sT + (w << 9), l, tw);

    // per-element: bin at fftshifted coordinates
    int   c   = c0 + w;
    float sxf = (float)((c + 256) & 511) - 255.5f;
    float sx2 = sxf * sxf;
#pragma unroll
    for (int k = 0; k < 16; k++) {
        int   ky  = l + (k << 5);
        float syf = (float)((ky + 256) & 511) - 255.5f;
        int   bin = (int)sqrtf(sx2 + syf * syf);
        float2 P = sP[(w << 9) + ky];
        float2 T = sT[(w << 9) + ky];
        float p2 = P.x * P.x + P.y * P.y;
        float t2 = T.x * T.x + T.y * T.y;
        float df = p2 - t2;
        float d  = df * df;
        float re = P.x + 1e-8f;
        float mag = 10.0f * logf(re * re + P.y * P.y);   // 20*ln|comp|
        atomicAdd(&sbm[bin], mag);
        atomicAdd(&sbd[bin], d);
    }
    __syncthreads();

    for (int i = tid; i < NBINS; i += 256) {
        atomicAdd(&g_Smag[img][i], sbm[i]);
        atomicAdd(&g_Sd[img][i],   sbd[i]);
    }
}

// ---------------------------------------------------------------------------
// Pass 3: per-image normalize + weighted dot, single block of 512 threads.
__global__ void __launch_bounds__(512) kfinal(float* __restrict__ out) {
    __shared__ int   scnt[NBINS];
    __shared__ float bm[NBINS];
    __shared__ float rmn[512], rmx[512];
    __shared__ double racc[512];

    int tid = threadIdx.x;
    for (int i = tid; i < NBINS; i += 512) scnt[i] = 0;
    __syncthreads();

    // bin counts (constant, cheap to recompute: deterministic per call)
    for (int idx = tid; idx < NPIX; idx += 512) {
        int y = idx >> 9, x = idx & 511;
        float dy = (float)y - 255.5f;
        float dx = (float)x - 255.5f;
        int bin = (int)sqrtf(dx * dx + dy * dy);
        atomicAdd(&scnt[bin], 1);
    }
    __syncthreads();

    double acc = 0.0;
    for (int img = 0; img < NIMG; img++) {
        if (tid < NBINS) bm[tid] = g_Smag[img][tid] / (float)scnt[tid];
        __syncthreads();

        // min/max over bins 1..360
        float mn = CUDART_INF_F, mx = -CUDART_INF_F;
        if (tid >= 1 && tid <= 360) { mn = bm[tid]; mx = bm[tid]; }
        rmn[tid] = mn; rmx[tid] = mx;
        __syncthreads();
        for (int off = 256; off > 0; off >>= 1) {
            if (tid < off) {
                rmn[tid] = fminf(rmn[tid], rmn[tid + off]);
                rmx[tid] = fmaxf(rmx[tid], rmx[tid + off]);
            }
            __syncthreads();
        }
        float fmn = rmn[0], fmx = rmx[0];

        if (tid < NBINS) {
            float psdext;
            if (tid == 361) {
                psdext = 0.0f;
            } else {
                int bb = (tid == 0) ? 1 : tid;     // psd_ext[0] == psd_ext[1]
                psdext = (bm[bb] - fmn) / (fmx - fmn);
            }
            float wv = 1.0f - psdext;
            if (!(wv == wv)) wv = 0.0f;            // nan -> 0
            wv = fminf(fmaxf(wv, 0.0f), 1.0f);     // clip
            acc += (double)wv * (double)g_Sd[img][tid];
        }
        __syncthreads();
    }

    racc[tid] = acc;
    __syncthreads();
    for (int off = 256; off > 0; off >>= 1) {
        if (tid < off) racc[tid] += racc[tid + off];
        __syncthreads();
    }
    if (tid == 0) out[0] = (float)(racc[0] / (double)(NIMG * (size_t)NPIX));
}

// ---------------------------------------------------------------------------
extern "C" void kernel_launch(void* const* d_in, const int* in_sizes, int n_in,
                              void* d_out, int out_size) {
    const float* pred = (const float*)d_in[0];
    const float* tgt  = (const float*)d_in[1];
    float* out = (float*)d_out;

    static bool attr_set = false;
    const int smemB = (8 * HH * 2 + 256) * (int)sizeof(float2)
                      + 2 * NBINS * (int)sizeof(float);
    if (!attr_set) {
        cudaFuncSetAttribute(kfft_cols,
                             cudaFuncAttributeMaxDynamicSharedMemorySize, smemB);
        attr_set = true;
    }

    kzero<<<(NIMG * NBINS + 255) / 256, 256>>>();
    kfft_rows<<<48 * 64, 256>>>(pred, tgt);
    kfft_cols<<<NIMG * 64, 256, smemB>>>();
    kfinal<<<1, 512>>>(out);
}

// round 4
// speedup vs baseline: 1.7716x; 1.7716x over previous
#include <cuda_runtime.h>
#include <math_constants.h>

#define HH 512
#define WW 512
#define NIMG 24          // 8 * 3 image slices per tensor
#define NBINS 362
#define NPIX (HH * WW)
#define WP 264           // padded scratch row stride (float2); cols 0..256 valid
#define CSTR 514         // padded smem column stride (float2) to reduce bank conflicts

// ---------------------------------------------------------------------------
// Scratch: only columns 0..256 of the row FFT are stored (Hermitian symmetry).
__device__ float2 g_fft[2][NIMG][HH * WP];
__device__ float  g_Smag[NIMG][NBINS];
__device__ float  g_Sd[NIMG][NBINS];
__device__ float  g_cnt[NBINS];

// ---------------------------------------------------------------------------
// Warp-synchronous 512-pt radix-2 DIT FFT (bit-reversed input, natural output).
__device__ __forceinline__ void fft512(float2* buf, int lane, const float2* tw) {
#pragma unroll
    for (int s = 1; s <= 9; s++) {
        const int half = 1 << (s - 1);
#pragma unroll
        for (int k = 0; k < 8; k++) {
            int t  = lane + (k << 5);
            int j  = t & (half - 1);
            int i0 = ((t >> (s - 1)) << s) + j;
            int i1 = i0 + half;
            float2 W = tw[j << (9 - s)];
            float2 u = buf[i0];
            float2 v = buf[i1];
            float2 vw = make_float2(v.x * W.x - v.y * W.y,
                                    v.x * W.y + v.y * W.x);
            buf[i0] = make_float2(u.x + vw.x, u.y + vw.y);
            buf[i1] = make_float2(u.x - vw.x, u.y - vw.y);
        }
        __syncwarp();
    }
}

__device__ __forceinline__ int rev9(int x) {
    return (int)(__brev((unsigned)x) >> 23);
}

// ---------------------------------------------------------------------------
__global__ void kzero() {
    int i = blockIdx.x * blockDim.x + threadIdx.x;
    int tot = NIMG * NBINS;
    if (i < tot) { ((float*)g_Smag)[i] = 0.0f; ((float*)g_Sd)[i] = 0.0f; }
    if (i < NBINS) g_cnt[i] = 0.0f;
}

// ---------------------------------------------------------------------------
// Pass 1: row FFTs, 2 real rows packed per complex FFT. 8 pairs (16 rows)
// per block. grid = 48 slices * 32 pair-groups = 1536.
__global__ void __launch_bounds__(256) kfft_rows(const float* __restrict__ pred,
                                                 const float* __restrict__ tgt) {
    __shared__ float2 buf[8][HH];
    __shared__ float2 tw[256];

    int tid = threadIdx.x;
    {
        float sn, cs;
        sincospif(-(float)tid / 256.0f, &sn, &cs);
        tw[tid] = make_float2(cs, sn);
    }

    int bid   = blockIdx.x;
    int slice = bid >> 5;          // 0..47
    int pg    = bid & 31;          // pair group
    int tens  = (slice >= NIMG) ? 1 : 0;
    int img   = tens ? slice - NIMG : slice;
    const float* src = tens ? tgt : pred;

    int w = tid >> 5, l = tid & 31;
    int p = pg * 8 + w;            // pair index 0..255 -> rows 2p, 2p+1
    const float* rowA = src + ((size_t)img << 18) + ((size_t)(2 * p) << 9);
    const float* rowB = rowA + HH;

#pragma unroll
    for (int k = 0; k < 16; k++) {
        int x = l + (k << 5);
        buf[w][rev9(x)] = make_float2(rowA[x], rowB[x]);
    }
    __syncthreads();   // tw visible

    fft512(&buf[w][0], l, tw);

    // extract two real-row spectra, keep k = 0..256 only
    float2* dstA = g_fft[tens][img] + (size_t)(2 * p) * WP;
    float2* dstB = dstA + WP;
    for (int k = l; k <= 256; k += 32) {
        int m = (512 - k) & 511;
        float2 Z1 = buf[w][k];
        float2 Z2 = buf[w][m];
        dstA[k] = make_float2(0.5f * (Z1.x + Z2.x), 0.5f * (Z1.y - Z2.y));
        dstB[k] = make_float2(0.5f * (Z1.y + Z2.y), 0.5f * (Z2.x - Z1.x));
    }
}

// ---------------------------------------------------------------------------
// Pass 2: column FFTs for kx = 0..256 only; Hermitian mirror handled in
// binning. 8 columns per block; grid = 24 imgs * 33 groups = 792.
// img==0 blocks also accumulate the radius-bin pixel counts.
__global__ void __launch_bounds__(256) kfft_cols() {
    extern __shared__ unsigned char sraw[];
    float2* sP  = (float2*)sraw;              // 8*CSTR
    float2* sT  = sP + 8 * CSTR;              // 8*CSTR
    float2* tw  = sT + 8 * CSTR;              // 256
    float*  sbm = (float*)(tw + 256);         // NBINS
    float*  sbd = sbm + NBINS;                // NBINS
    float*  scn = sbd + NBINS;                // NBINS

    int tid = threadIdx.x;
    {
        float sn, cs;
        sincospif(-(float)tid / 256.0f, &sn, &cs);
        tw[tid] = make_float2(cs, sn);
    }
    for (int i = tid; i < NBINS; i += 256) { sbm[i] = 0.0f; sbd[i] = 0.0f; scn[i] = 0.0f; }

    int bid = blockIdx.x;
    int img = bid / 33;
    int c0  = (bid % 33) << 3;
    bool docnt = (img == 0);

    const float2* srcP = g_fft[0][img];
    const float2* srcT = g_fft[1][img];

    // load 512 x 8 tile (both tensors), bit-reversed + transposed in smem
    for (int i = tid; i < 8 * HH; i += 256) {
        int cx = i & 7, y = i >> 3;
        int r  = rev9(y);
        size_t off = (size_t)y * WP + c0 + cx;   // in-bounds: c0+cx <= 263 < WP
        sP[cx * CSTR + r] = srcP[off];
        sT[cx * CSTR + r] = srcT[off];
    }
    __syncthreads();

    int w = tid >> 5, l = tid & 31;
    int c = c0 + w;
    bool valid = (c <= 256);

    if (valid) {
        fft512(sP + w * CSTR, l, tw);
        fft512(sT + w * CSTR, l, tw);

        bool dup = (c >= 1 && c <= 255);         // mirror column 512-c not computed
        float sx   = (float)((c + 256) & 511) - 255.5f;
        float sxm  = 0.5f - (float)c;            // shifted coord of column 512-c
        float sx2  = sx * sx;
        float sxm2 = sxm * sxm;
#pragma unroll
        for (int k = 0; k < 16; k++) {
            int   ky = l + (k << 5);
            float2 P = sP[w * CSTR + ky];
            float2 T = sT[w * CSTR + ky];
            float p2 = P.x * P.x + P.y * P.y;
            float t2 = T.x * T.x + T.y * T.y;
            float df = p2 - t2;
            float d  = df * df;
            float re = P.x + 1e-8f;
            float mag = 10.0f * logf(re * re + P.y * P.y);  // 20*ln|re+eps + i*im|

            float sy = (float)((ky + 256) & 511) - 255.5f;
            int b1 = (int)sqrtf(sx2 + sy * sy);
            atomicAdd(sbm + b1, mag);
            atomicAdd(sbd + b1, d);
            if (docnt) atomicAdd(scn + b1, 1.0f);

            if (dup) {   // conj-mirror pixel ((-ky)&511, 512-c): same mag/d
                int   ky2 = (512 - ky) & 511;
                float sy2 = (float)((ky2 + 256) & 511) - 255.5f;
                int b2 = (int)sqrtf(sxm2 + sy2 * sy2);
                atomicAdd(sbm + b2, mag);
                atomicAdd(sbd + b2, d);
                if (docnt) atomicAdd(scn + b2, 1.0f);
            }
        }
    }
    __syncthreads();

    for (int i = tid; i < NBINS; i += 256) {
        atomicAdd(&g_Smag[img][i], sbm[i]);
        atomicAdd(&g_Sd[img][i],   sbd[i]);
        if (docnt) atomicAdd(&g_cnt[i], scn[i]);
    }
}

// ---------------------------------------------------------------------------
// Pass 3: per-image normalize + weighted dot. Pure per-bin work now.
__global__ void __launch_bounds__(512) kfinal(float* __restrict__ out) {
    __shared__ float bm[NBINS];
    __shared__ float rmn[512], rmx[512];
    __shared__ double racc[512];

    int tid = threadIdx.x;
    double acc = 0.0;

    for (int img = 0; img < NIMG; img++) {
        if (tid < NBINS) bm[tid] = g_Smag[img][tid] / g_cnt[tid];
        __syncthreads();

        float mn = CUDART_INF_F, mx = -CUDART_INF_F;
        if (tid >= 1 && tid <= 360) { mn = bm[tid]; mx = bm[tid]; }
        rmn[tid] = mn; rmx[tid] = mx;
        __syncthreads();
        for (int off = 256; off > 0; off >>= 1) {
            if (tid < off) {
                rmn[tid] = fminf(rmn[tid], rmn[tid + off]);
                rmx[tid] = fmaxf(rmx[tid], rmx[tid + off]);
            }
            __syncthreads();
        }
        float fmn = rmn[0], fmx = rmx[0];

        if (tid < NBINS) {
            float psdext;
            if (tid == 361) {
                psdext = 0.0f;
            } else {
                int bb = (tid == 0) ? 1 : tid;   // psd_ext[0] == psd_ext[1]
                psdext = (bm[bb] - fmn) / (fmx - fmn);
            }
            float wv = 1.0f - psdext;
            if (!(wv == wv)) wv = 0.0f;          // nan -> 0
            wv = fminf(fmaxf(wv, 0.0f), 1.0f);   // clip
            acc += (double)wv * (double)g_Sd[img][tid];
        }
        __syncthreads();
    }

    racc[tid] = acc;
    __syncthreads();
    for (int off = 256; off > 0; off >>= 1) {
        if (tid < off) racc[tid] += racc[tid + off];
        __syncthreads();
    }
    if (tid == 0) out[0] = (float)(racc[0] / ((double)NIMG * (double)NPIX));
}

// ---------------------------------------------------------------------------
extern "C" void kernel_launch(void* const* d_in, const int* in_sizes, int n_in,
                              void* d_out, int out_size) {
    const float* pred = (const float*)d_in[0];
    const float* tgt  = (const float*)d_in[1];
    float* out = (float*)d_out;

    const int smemB = (2 * 8 * CSTR + 256) * (int)sizeof(float2)
                      + 3 * NBINS * (int)sizeof(float);
    cudaFuncSetAttribute(kfft_cols,
                         cudaFuncAttributeMaxDynamicSharedMemorySize, smemB);

    kzero<<<(NIMG * NBINS + 255) / 256, 256>>>();
    kfft_rows<<<48 * 32, 256>>>(pred, tgt);
    kfft_cols<<<NIMG * 33, 256, smemB>>>();
    kfinal<<<1, 512>>>(out);
}

// round 6
// speedup vs baseline: 2.2332x; 1.2605x over previous
#include <cuda_runtime.h>
#include <math_constants.h>

#define HH 512
#define WW 512
#define NIMG 24          // 8 * 3 image slices per tensor
#define NBINS 362
#define NPIX (HH * WW)
#define WP 264           // padded scratch row stride (float2); cols 0..256 valid
#define CST 516          // padded smem column stride (float2)

// swizzle for warp-private 512-float2 smem buffer (conflict-free both ways)
#define SWZ(t) ((t) ^ (((t) >> 4) & 15))

// ---------------------------------------------------------------------------
__device__ float2 g_fft[2][NIMG][HH * WP];
__device__ float  g_Smag[NIMG][NBINS];
__device__ float  g_Sd[NIMG][NBINS];
__device__ float  g_cnt[NBINS];
__device__ double g_part[NIMG];

__device__ __forceinline__ int rev5(int x) { return (int)(__brev((unsigned)x) >> 27); }

// ---------------------------------------------------------------------------
// Fully register-resident 512-pt radix-2 DIT FFT per warp.
// reg[r] holds logical element t = lane*16 + r; input must be loaded so that
// reg[r] = x[rev9(lane*16+r)] = x[rev4(r)*32 + rev5(lane)].
// tw[k] = exp(-2*pi*i*k/512), k in [0,256).
__device__ __forceinline__ void rfft512(float2 reg[16], int lane, const float2* tw) {
    const float c16[8] = { 1.f,  0.92387953f,  0.70710678f,  0.38268343f,
                           0.f, -0.38268343f, -0.70710678f, -0.92387953f };
    const float s16[8] = { 0.f, -0.38268343f, -0.70710678f, -0.92387953f,
                          -1.f, -0.92387953f, -0.70710678f, -0.38268343f };
    // stages 1-4: intra-lane, constant twiddles
#pragma unroll
    for (int s = 1; s <= 4; s++) {
        const int half = 1 << (s - 1);
#pragma unroll
        for (int b = 0; b < 8; b++) {
            int j  = b & (half - 1);
            int i0 = ((b >> (s - 1)) << s) + j;
            int i1 = i0 + half;
            int ji = j << (4 - s);                  // W = W16^ji
            float2 u = reg[i0], v = reg[i1];
            float2 wv = make_float2(v.x * c16[ji] - v.y * s16[ji],
                                    v.x * s16[ji] + v.y * c16[ji]);
            reg[i0] = make_float2(u.x + wv.x, u.y + wv.y);
            reg[i1] = make_float2(u.x - wv.x, u.y - wv.y);
        }
    }
    // stages 5-9: cross-lane via shfl.xor
#pragma unroll
    for (int s = 5; s <= 9; s++) {
        const int L = 1 << (s - 5);
        int m = lane & (L - 1);
        float es, ec;
        sincospif(-(float)m / (float)L, &es, &ec);  // E = e^{-i*pi*m/L}
        const bool  up  = (lane & L) != 0;
        const float sgn = up ? -1.f : 1.f;
#pragma unroll
        for (int r = 0; r < 16; r++) {
            float2 x = reg[r];
            float2 ox;
            ox.x = __shfl_xor_sync(0xffffffffu, x.x, L);
            ox.y = __shfl_xor_sync(0xffffffffu, x.y, L);
            float2 u = up ? ox : x;
            float2 v = up ? x : ox;
            float2 ev = make_float2(v.x * ec - v.y * es,
                                    v.x * es + v.y * ec);
            float2 C = tw[(r << 4) >> (s - 5)];     // broadcast, conflict-free
            float2 wv = make_float2(ev.x * C.x - ev.y * C.y,
                                    ev.x * C.y + ev.y * C.x);
            reg[r].x = fmaf(sgn, wv.x, u.x);
            reg[r].y = fmaf(sgn, wv.y, u.y);
        }
    }
}

// ---------------------------------------------------------------------------
__global__ void kzero() {
    int i = blockIdx.x * blockDim.x + threadIdx.x;
    if (i < NIMG * NBINS) { ((float*)g_Smag)[i] = 0.0f; ((float*)g_Sd)[i] = 0.0f; }
    if (i < NBINS) g_cnt[i] = 0.0f;
}

// ---------------------------------------------------------------------------
// Pass 1: row FFTs, 2 real rows packed per complex FFT, register FFT.
// 8 warps/block = 8 row-pairs. grid = 48 slices * 32 groups.
__global__ void __launch_bounds__(256) kfft_rows(const float* __restrict__ pred,
                                                 const float* __restrict__ tgt) {
    __shared__ float2 sbuf[8][512];
    __shared__ float2 tw[256];
    const int REV4[16] = {0,8,4,12,2,10,6,14,1,9,5,13,3,11,7,15};

    int tid = threadIdx.x;
    {
        float sn, cs;
        sincospif(-(float)tid / 256.0f, &sn, &cs);
        tw[tid] = make_float2(cs, sn);
    }

    int bid   = blockIdx.x;
    int slice = bid >> 5;
    int pg    = bid & 31;
    int tens  = (slice >= NIMG) ? 1 : 0;
    int img   = tens ? slice - NIMG : slice;
    const float* src = tens ? tgt : pred;

    int w = tid >> 5, lane = tid & 31;
    int p = pg * 8 + w;                          // rows 2p, 2p+1
    const float* rowA = src + ((size_t)img << 18) + ((size_t)(2 * p) << 9);
    const float* rowB = rowA + HH;
    int lr = rev5(lane);

    float2 reg[16];
#pragma unroll
    for (int r = 0; r < 16; r++) {
        int s = REV4[r] * 32 + lr;               // = rev9(lane*16 + r)
        reg[r] = make_float2(rowA[s], rowB[s]);
    }
    __syncthreads();                             // tw ready

    rfft512(reg, lane, tw);

    // spill to warp-private swizzled smem for the Hermitian unpack
#pragma unroll
    for (int r = 0; r < 16; r++) {
        int t = lane * 16 + r;
        sbuf[w][SWZ(t)] = reg[r];
    }
    __syncwarp();

    float2* dstA = g_fft[tens][img] + (size_t)(2 * p) * WP;
    float2* dstB = dstA + WP;
    for (int k = lane; k <= 256; k += 32) {
        int m = (512 - k) & 511;
        float2 Z1 = sbuf[w][SWZ(k)];
        float2 Z2 = sbuf[w][SWZ(m)];
        dstA[k] = make_float2(0.5f * (Z1.x + Z2.x), 0.5f * (Z1.y - Z2.y));
        dstB[k] = make_float2(0.5f * (Z1.y + Z2.y), 0.5f * (Z2.x - Z1.x));
    }
}

// ---------------------------------------------------------------------------
// Pass 2: column register FFTs for kx = 0..256; Hermitian mirror in binning.
// 1 warp = 1 column (both tensors). grid = 24 * 33.
__global__ void __launch_bounds__(256) kfft_cols() {
    extern __shared__ unsigned char sraw[];
    float2* sP  = (float2*)sraw;                 // 8*CST
    float2* sT  = sP + 8 * CST;                  // 8*CST
    float2* tw  = sT + 8 * CST;                  // 256
    float*  sbm = (float*)(tw + 256);            // NBINS
    float*  sbd = sbm + NBINS;
    float*  scn = sbd + NBINS;
    const int REV4[16] = {0,8,4,12,2,10,6,14,1,9,5,13,3,11,7,15};

    int tid = threadIdx.x;
    {
        float sn, cs;
        sincospif(-(float)tid / 256.0f, &sn, &cs);
        tw[tid] = make_float2(cs, sn);
    }
    for (int i = tid; i < NBINS; i += 256) { sbm[i] = 0.0f; sbd[i] = 0.0f; scn[i] = 0.0f; }

    int bid = blockIdx.x;
    int img = bid / 33;
    int c0  = (bid % 33) << 3;
    bool docnt = (img == 0);

    const float2* srcP = g_fft[0][img];
    const float2* srcT = g_fft[1][img];

    // stage 512 x 8 tile, transposed (coalesced 64B global chunks)
    for (int i = tid; i < 8 * HH; i += 256) {
        int cx = i & 7, y = i >> 3;
        size_t off = (size_t)y * WP + c0 + cx;
        sP[cx * CST + y] = srcP[off];
        sT[cx * CST + y] = srcT[off];
    }
    __syncthreads();

    int w = tid >> 5, lane = tid & 31;
    int c = c0 + w;
    if (c <= 256) {
        int lr = rev5(lane);
        float2* colP = sP + w * CST;
        float2* colT = sT + w * CST;

        float2 reg[16];
#pragma unroll
        for (int r = 0; r < 16; r++) reg[r] = colP[REV4[r] * 32 + lr];
        rfft512(reg, lane, tw);

        float p2[16], mg[16];
#pragma unroll
        for (int r = 0; r < 16; r++) {
            float2 P = reg[r];
            p2[r] = P.x * P.x + P.y * P.y;
            float re = P.x + 1e-8f;
            mg[r] = 10.0f * logf(re * re + P.y * P.y);   // 20*ln|re+eps + i*im|
        }

#pragma unroll
        for (int r = 0; r < 16; r++) reg[r] = colT[REV4[r] * 32 + lr];
        rfft512(reg, lane, tw);

        bool dup = (c >= 1 && c <= 255);
        float sx   = (float)((c + 256) & 511) - 255.5f;
        float sxm  = 0.5f - (float)c;
        float sx2  = sx * sx;
        float sxm2 = sxm * sxm;
#pragma unroll
        for (int r = 0; r < 16; r++) {
            int ky = lane * 16 + r;
            float t2 = reg[r].x * reg[r].x + reg[r].y * reg[r].y;
            float df = p2[r] - t2;
            float d  = df * df;
            float mag = mg[r];

            float sy = (float)((ky + 256) & 511) - 255.5f;
            int b1 = (int)sqrtf(sx2 + sy * sy);
            atomicAdd(sbm + b1, mag);
            atomicAdd(sbd + b1, d);
            if (docnt) atomicAdd(scn + b1, 1.0f);

            if (dup) {   // conjugate-mirror pixel: identical mag/d, mirrored bin
                int   ky2 = (512 - ky) & 511;
                float sy2 = (float)((ky2 + 256) & 511) - 255.5f;
                int b2 = (int)sqrtf(sxm2 + sy2 * sy2);
                atomicAdd(sbm + b2, mag);
                atomicAdd(sbd + b2, d);
                if (docnt) atomicAdd(scn + b2, 1.0f);
            }
        }
    }
    __syncthreads();

    for (int i = tid; i < NBINS; i += 256) {
        atomicAdd(&g_Smag[img][i], sbm[i]);
        atomicAdd(&g_Sd[img][i],   sbd[i]);
        if (docnt) atomicAdd(&g_cnt[i], scn[i]);
    }
}

// ---------------------------------------------------------------------------
// Pass 3a: per-image normalize + weighted dot. One block per image.
__global__ void __launch_bounds__(512) kimg() {
    __shared__ float bm[NBINS];
    __shared__ float rmn[512], rmx[512];
    __shared__ double racc[512];

    int tid = threadIdx.x;
    int img = blockIdx.x;

    if (tid < NBINS) bm[tid] = g_Smag[img][tid] / g_cnt[tid];
    __syncthreads();

    float mn = CUDART_INF_F, mx = -CUDART_INF_F;
    if (tid >= 1 && tid <= 360) { mn = bm[tid]; mx = bm[tid]; }
    rmn[tid] = mn; rmx[tid] = mx;
    __syncthreads();
    for (int off = 256; off > 0; off >>= 1) {
        if (tid < off) {
            rmn[tid] = fminf(rmn[tid], rmn[tid + off]);
            rmx[tid] = fmaxf(rmx[tid], rmx[tid + off]);
        }
        __syncthreads();
    }
    float fmn = rmn[0], fmx = rmx[0];

    double acc = 0.0;
    if (tid < NBINS) {
        float psdext;
        if (tid == 361) {
            psdext = 0.0f;
        } else {
            int bb = (tid == 0) ? 1 : tid;       // psd_ext[0] == psd_ext[1]
            psdext = (bm[bb] - fmn) / (fmx - fmn);
        }
        float wv = 1.0f - psdext;
        if (!(wv == wv)) wv = 0.0f;              // nan -> 0
        wv = fminf(fmaxf(wv, 0.0f), 1.0f);       // clip
        acc = (double)wv * (double)g_Sd[img][tid];
    }
    racc[tid] = acc;
    __syncthreads();
    for (int off = 256; off > 0; off >>= 1) {
        if (tid < off) racc[tid] += racc[tid + off];
        __syncthreads();
    }
    if (tid == 0) g_part[img] = racc[0];
}

// Pass 3b: deterministic final sum.
__global__ void ksum(float* __restrict__ out) {
    if (threadIdx.x == 0) {
        double a = 0.0;
        for (int i = 0; i < NIMG; i++) a += g_part[i];
        out[0] = (float)(a / ((double)NIMG * (double)NPIX));
    }
}

// ---------------------------------------------------------------------------
extern "C" void kernel_launch(void* const* d_in, const int* in_sizes, int n_in,
                              void* d_out, int out_size) {
    const float* pred = (const float*)d_in[0];
    const float* tgt  = (const float*)d_in[1];
    float* out = (float*)d_out;

    const int smemB = (2 * 8 * CST + 256) * (int)sizeof(float2)
                      + 3 * NBINS * (int)sizeof(float);
    cudaFuncSetAttribute(kfft_cols,
                         cudaFuncAttributeMaxDynamicSharedMemorySize, smemB);

    kzero<<<(NIMG * NBINS + 255) / 256, 256>>>();
    kfft_rows<<<48 * 32, 256>>>(pred, tgt);
    kfft_cols<<<NIMG * 33, 256, smemB>>>();
    kimg<<<NIMG, 512>>>();
    ksum<<<1, 32>>>(out);
}

// round 8
// speedup vs baseline: 2.8910x; 1.2946x over previous
#include <cuda_runtime.h>
#include <math_constants.h>

#define HH 512
#define WW 512
#define NIMG 24          // 8 * 3 image slices per tensor
#define NBINS 362
#define NPIX (HH * WW)
#define NK 257           // stored spectrum columns 0..256 (Hermitian)

// swizzle for warp-private 512-float2 smem buffer (conflict-free both ways)
#define SWZ(t) ((t) ^ (((t) >> 4) & 15))

// ---------------------------------------------------------------------------
// Transposed scratch: g_fftT[tens][img][k*512 + y] = row-FFT(row y)[freq k]
__device__ float2 g_fftT[2][NIMG][NK * HH];
__device__ float  g_Smag[NIMG][NBINS];
__device__ float  g_Sd[NIMG][NBINS];
__device__ float  g_cnt[NBINS];
__device__ double g_part[NIMG];

__device__ __forceinline__ int rev5(int x) { return (int)(__brev((unsigned)x) >> 27); }

// ---------------------------------------------------------------------------
// Fully register-resident 512-pt radix-2 DIT FFT per warp.
// reg[r] = x[rev9(lane*16+r)] on входе; natural order on exit (t = lane*16+r).
// tw[k] = exp(-2*pi*i*k/512), k in [0,256).
__device__ __forceinline__ void rfft512(float2 reg[16], int lane, const float2* tw) {
    const float c16[8] = { 1.f,  0.92387953f,  0.70710678f,  0.38268343f,
                           0.f, -0.38268343f, -0.70710678f, -0.92387953f };
    const float s16[8] = { 0.f, -0.38268343f, -0.70710678f, -0.92387953f,
                          -1.f, -0.92387953f, -0.70710678f, -0.38268343f };
    // stages 1-4: intra-lane, constant twiddles
#pragma unroll
    for (int s = 1; s <= 4; s++) {
        const int half = 1 << (s - 1);
#pragma unroll
        for (int b = 0; b < 8; b++) {
            int j  = b & (half - 1);
            int i0 = ((b >> (s - 1)) << s) + j;
            int i1 = i0 + half;
            int ji = j << (4 - s);
            float2 u = reg[i0], v = reg[i1];
            float2 wv = make_float2(v.x * c16[ji] - v.y * s16[ji],
                                    v.x * s16[ji] + v.y * c16[ji]);
            reg[i0] = make_float2(u.x + wv.x, u.y + wv.y);
            reg[i1] = make_float2(u.x - wv.x, u.y - wv.y);
        }
    }
    // stages 5-9: cross-lane via shfl.xor; E = exp(-i*pi*m/L) from the table
#pragma unroll
    for (int s = 5; s <= 9; s++) {
        const int L = 1 << (s - 5);
        int m = lane & (L - 1);
        float2 E = tw[m << (13 - s)];
        float ec = E.x, es = E.y;
        const bool  up  = (lane & L) != 0;
        const float sgn = up ? -1.f : 1.f;
#pragma unroll
        for (int r = 0; r < 16; r++) {
            float2 x = reg[r];
            float2 ox;
            ox.x = __shfl_xor_sync(0xffffffffu, x.x, L);
            ox.y = __shfl_xor_sync(0xffffffffu, x.y, L);
            float2 u = up ? ox : x;
            float2 v = up ? x : ox;
            float2 ev = make_float2(v.x * ec - v.y * es,
                                    v.x * es + v.y * ec);
            float2 C = tw[(r << 4) >> (s - 5)];
            float2 wv = make_float2(ev.x * C.x - ev.y * C.y,
                                    ev.x * C.y + ev.y * C.x);
            reg[r].x = fmaf(sgn, wv.x, u.x);
            reg[r].y = fmaf(sgn, wv.y, u.y);
        }
    }
}

// ---------------------------------------------------------------------------
// Pass 1: row FFTs (2 real rows packed per complex FFT) + transposed store.
// 8 warps/block = 16 rows. grid = 48 slices * 32 groups = 1536.
// Blocks 0..17 also zero the bin accumulators (ready before pass 2).
__global__ void __launch_bounds__(256) kfft_rows(const float* __restrict__ pred,
                                                 const float* __restrict__ tgt) {
    extern __shared__ float2 dsm[];
    float2* sbuf  = dsm;              // 8 * 512
    float2* ttile = dsm + 4096;       // 257 * 17 (padded)
    float2* tw    = ttile + NK * 17;  // 256
    const int REV4[16] = {0,8,4,12,2,10,6,14,1,9,5,13,3,11,7,15};

    int tid = threadIdx.x;
    int bid = blockIdx.x;

    if (bid < 18) {   // fold kzero in here (completes before pass 2 launch)
        for (int i = bid * 256 + tid; i < NIMG * NBINS; i += 18 * 256) {
            ((float*)g_Smag)[i] = 0.0f;
            ((float*)g_Sd)[i]   = 0.0f;
        }
        if (bid == 0)
            for (int i = tid; i < NBINS; i += 256) g_cnt[i] = 0.0f;
    }
    {
        float sn, cs;
        sincospif(-(float)tid / 256.0f, &sn, &cs);
        tw[tid] = make_float2(cs, sn);
    }

    int slice = bid >> 5;
    int pg    = bid & 31;
    int tens  = (slice >= NIMG) ? 1 : 0;
    int img   = tens ? slice - NIMG : slice;
    const float* src = tens ? tgt : pred;

    int w = tid >> 5, lane = tid & 31;
    int y0 = pg * 16;
    const float* rowA = src + ((size_t)img << 18) + ((size_t)(y0 + 2 * w) << 9);
    const float* rowB = rowA + HH;
    int lr = rev5(lane);

    float2 reg[16];
#pragma unroll
    for (int r = 0; r < 16; r++) {
        int s = REV4[r] * 32 + lr;
        reg[r] = make_float2(rowA[s], rowB[s]);
    }
    __syncthreads();                 // tw ready

    rfft512(reg, lane, tw);

#pragma unroll
    for (int r = 0; r < 16; r++) {
        int t = lane * 16 + r;
        sbuf[(w << 9) + SWZ(t)] = reg[r];
    }
    __syncwarp();

    // Hermitian unpack -> transposed smem tile
    for (int k = lane; k <= 256; k += 32) {
        int m = (512 - k) & 511;
        float2 Z1 = sbuf[(w << 9) + SWZ(k)];
        float2 Z2 = sbuf[(w << 9) + SWZ(m)];
        ttile[k * 17 + 2 * w]     = make_float2(0.5f * (Z1.x + Z2.x), 0.5f * (Z1.y - Z2.y));
        ttile[k * 17 + 2 * w + 1] = make_float2(0.5f * (Z1.y + Z2.y), 0.5f * (Z2.x - Z1.x));
    }
    __syncthreads();

    // coalesced transposed store: 16 consecutive y per k = 128B lines
    float2* outp = g_fftT[tens][img];
    for (int i = tid; i < NK * 16; i += 256) {
        int k = i >> 4, y = i & 15;
        outp[k * 512 + y0 + y] = ttile[k * 17 + y];
    }
}

// ---------------------------------------------------------------------------
// Pass 2: column register FFTs for kx = 0..256, direct global loads
// (no staging), run-aggregated bin atomics. 1 warp = 1 column. grid = 24*33.
__global__ void __launch_bounds__(256) kfft_cols() {
    __shared__ float2 tw[256];
    __shared__ float  sbm[NBINS], sbd[NBINS], scn[NBINS];
    const int REV4[16] = {0,8,4,12,2,10,6,14,1,9,5,13,3,11,7,15};

    int tid = threadIdx.x;
    {
        float sn, cs;
        sincospif(-(float)tid / 256.0f, &sn, &cs);
        tw[tid] = make_float2(cs, sn);
    }
    for (int i = tid; i < NBINS; i += 256) { sbm[i] = 0.0f; sbd[i] = 0.0f; scn[i] = 0.0f; }
    __syncthreads();

    int bid = blockIdx.x;
    int img = bid / 33;
    int c0  = (bid % 33) << 3;
    bool docnt = (img == 0);

    int w = tid >> 5, lane = tid & 31;
    int c = c0 + w;

    if (c <= 256) {
        const float2* colP = &g_fftT[0][img][(size_t)c * 512];
        const float2* colT = &g_fftT[1][img][(size_t)c * 512];
        int lr = rev5(lane);

        float2 reg[16];
#pragma unroll
        for (int r = 0; r < 16; r++) reg[r] = colP[REV4[r] * 32 + lr];
        rfft512(reg, lane, tw);

        float p2[16], mg[16];
#pragma unroll
        for (int r = 0; r < 16; r++) {
            float2 P = reg[r];
            p2[r] = P.x * P.x + P.y * P.y;
            float re = P.x + 1e-8f;
            mg[r] = 10.0f * __logf(re * re + P.y * P.y);   // 20*ln|re+eps + i*im|
        }

#pragma unroll
        for (int r = 0; r < 16; r++) reg[r] = colT[REV4[r] * 32 + lr];
        rfft512(reg, lane, tw);

        bool dup = (c >= 1 && c <= 255);
        float sx   = (float)((c + 256) & 511) - 255.5f;
        float sxm  = 0.5f - (float)c;
        float sx2  = sx * sx;
        float sxm2 = sxm * sxm;

        // run-aggregated binning: bins monotone in r within a thread
        int   pb1 = -1, pb2 = -1;
        float am1 = 0.f, ad1 = 0.f, cn1 = 0.f;
        float am2 = 0.f, ad2 = 0.f, cn2 = 0.f;
#pragma unroll
        for (int r = 0; r < 16; r++) {
            int ky = lane * 16 + r;
            float t2 = reg[r].x * reg[r].x + reg[r].y * reg[r].y;
            float df = p2[r] - t2;
            float d  = df * df;
            float mag = mg[r];

            float sy = (float)((ky + 256) & 511) - 255.5f;
            int b1 = (int)sqrtf(sx2 + sy * sy);
            if (b1 != pb1) {
                if (pb1 >= 0) {
                    atomicAdd(sbm + pb1, am1);
                    atomicAdd(sbd + pb1, ad1);
                    if (docnt) atomicAdd(scn + pb1, cn1);
                }
                pb1 = b1; am1 = 0.f; ad1 = 0.f; cn1 = 0.f;
            }
            am1 += mag; ad1 += d; cn1 += 1.f;

            if (dup) {   // conjugate-mirror pixel: same mag/d, mirrored bin
                int   ky2 = (512 - ky) & 511;
                float sy2 = (float)((ky2 + 256) & 511) - 255.5f;
                int b2 = (int)sqrtf(sxm2 + sy2 * sy2);
                if (b2 != pb2) {
                    if (pb2 >= 0) {
                        atomicAdd(sbm + pb2, am2);
                        atomicAdd(sbd + pb2, ad2);
                        if (docnt) atomicAdd(scn + pb2, cn2);
                    }
                    pb2 = b2; am2 = 0.f; ad2 = 0.f; cn2 = 0.f;
                }
                am2 += mag; ad2 += d; cn2 += 1.f;
            }
        }
        if (pb1 >= 0) {
            atomicAdd(sbm + pb1, am1);
            atomicAdd(sbd + pb1, ad1);
            if (docnt) atomicAdd(scn + pb1, cn1);
        }
        if (pb2 >= 0) {
            atomicAdd(sbm + pb2, am2);
            atomicAdd(sbd + pb2, ad2);
            if (docnt) atomicAdd(scn + pb2, cn2);
        }
    }
    __syncthreads();

    for (int i = tid; i < NBINS; i += 256) {
        atomicAdd(&g_Smag[img][i], sbm[i]);
        atomicAdd(&g_Sd[img][i],   sbd[i]);
        if (docnt) atomicAdd(&g_cnt[i], scn[i]);
    }
}

// ---------------------------------------------------------------------------
// Pass 3a: per-image normalize + weighted dot. One block per image.
__global__ void __launch_bounds__(512) kimg() {
    __shared__ float bm[NBINS];
    __shared__ float rmn[512], rmx[512];
    __shared__ double racc[512];

    int tid = threadIdx.x;
    int img = blockIdx.x;

    if (tid < NBINS) bm[tid] = g_Smag[img][tid] / g_cnt[tid];
    __syncthreads();

    float mn = CUDART_INF_F, mx = -CUDART_INF_F;
    if (tid >= 1 && tid <= 360) { mn = bm[tid]; mx = bm[tid]; }
    rmn[tid] = mn; rmx[tid] = mx;
    __syncthreads();
    for (int off = 256; off > 0; off >>= 1) {
        if (tid < off) {
            rmn[tid] = fminf(rmn[tid], rmn[tid + off]);
            rmx[tid] = fmaxf(rmx[tid], rmx[tid + off]);
        }
        __syncthreads();
    }
    float fmn = rmn[0], fmx = rmx[0];

    double acc = 0.0;
    if (tid < NBINS) {
        float psdext;
        if (tid == 361) {
            psdext = 0.0f;
        } else {
            int bb = (tid == 0) ? 1 : tid;       // psd_ext[0] == psd_ext[1]
            psdext = (bm[bb] - fmn) / (fmx - fmn);
        }
        float wv = 1.0f - psdext;
        if (!(wv == wv)) wv = 0.0f;              // nan -> 0
        wv = fminf(fmaxf(wv, 0.0f), 1.0f);       // clip
        acc = (double)wv * (double)g_Sd[img][tid];
    }
    racc[tid] = acc;
    __syncthreads();
    for (int off = 256; off > 0; off >>= 1) {
        if (tid < off) racc[tid] += racc[tid + off];
        __syncthreads();
    }
    if (tid == 0) g_part[img] = racc[0];
}

// Pass 3b: deterministic final sum.
__global__ void ksum(float* __restrict__ out) {
    if (threadIdx.x == 0) {
        double a = 0.0;
        for (int i = 0; i < NIMG; i++) a += g_part[i];
        out[0] = (float)(a / ((double)NIMG * (double)NPIX));
    }
}

// ---------------------------------------------------------------------------
extern "C" void kernel_launch(void* const* d_in, const int* in_sizes, int n_in,
                              void* d_out, int out_size) {
    const float* pred = (const float*)d_in[0];
    const float* tgt  = (const float*)d_in[1];
    float* out = (float*)d_out;

    const int rowSmem = (4096 + NK * 17 + 256) * (int)sizeof(float2);  // ~69.8 KB
    cudaFuncSetAttribute(kfft_rows,
                         cudaFuncAttributeMaxDynamicSharedMemorySize, rowSmem);

    kfft_rows<<<48 * 32, 256, rowSmem>>>(pred, tgt);
    kfft_cols<<<NIMG * 33, 256>>>();
    kimg<<<NIMG, 512>>>();
    ksum<<<1, 32>>>(out);
}

// round 9
// speedup vs baseline: 3.1890x; 1.1031x over previous
#include <cuda_runtime.h>
#include <math_constants.h>

#define HH 512
#define WW 512
#define NIMG 24          // 8 * 3 image slices per tensor
#define NBINS 362
#define NPIX (HH * WW)
#define NK 257           // stored spectrum columns 0..256 (Hermitian)

// swizzle for warp-private 512-float2 smem buffer (conflict-free both ways)
#define SWZ(t) ((t) ^ (((t) >> 4) & 15))

// ---------------------------------------------------------------------------
// Transposed scratch: g_fftT[tens][img][k*512 + y] = row-FFT(row y)[freq k]
__device__ float2 g_fftT[2][NIMG][NK * HH];
__device__ float  g_Smag[NIMG][NBINS];
__device__ float  g_Sd[NIMG][NBINS];
__device__ float  g_cnt[NBINS];
__device__ double g_acc;
__device__ unsigned g_done;

__device__ __forceinline__ int rev5(int x) { return (int)(__brev((unsigned)x) >> 27); }

__device__ __forceinline__ float2 cmul(float2 a, float2 b) {
    return make_float2(a.x * b.x - a.y * b.y, a.x * b.y + a.y * b.x);
}

// ---------------------------------------------------------------------------
// Fully register-resident 512-pt radix-2 DIT FFT per warp.
// Input: reg[r] = x[rev9(lane*16+r)]. Output: natural order, t = lane*16+r.
// tw[k] = exp(-2*pi*i*k/512), k in [0,256).
__device__ __forceinline__ void rfft512(float2 reg[16], int lane, const float2* tw) {
    const float c16[8] = { 1.f,  0.92387953f,  0.70710678f,  0.38268343f,
                           0.f, -0.38268343f, -0.70710678f, -0.92387953f };
    const float s16[8] = { 0.f, -0.38268343f, -0.70710678f, -0.92387953f,
                          -1.f, -0.92387953f, -0.70710678f, -0.38268343f };
    // stages 1-4: intra-lane, compile-time twiddles (trivial ones fold away)
#pragma unroll
    for (int s = 1; s <= 4; s++) {
        const int half = 1 << (s - 1);
#pragma unroll
        for (int b = 0; b < 8; b++) {
            int j  = b & (half - 1);
            int i0 = ((b >> (s - 1)) << s) + j;
            int i1 = i0 + half;
            int ji = j << (4 - s);
            float2 u = reg[i0], v = reg[i1];
            float2 wv = make_float2(v.x * c16[ji] - v.y * s16[ji],
                                    v.x * s16[ji] + v.y * c16[ji]);
            reg[i0] = make_float2(u.x + wv.x, u.y + wv.y);
            reg[i1] = make_float2(u.x - wv.x, u.y - wv.y);
        }
    }
    // stages 5-9: cross-lane, pre-twiddle form.
    // Full twiddle W = tw[(m*16+r)*2^(9-s)], m = lane & (L-1), L = 2^(s-5).
    //   s=5: m==0 -> W = tw[16r] (broadcast)        -> single cmul
    //   s=6: W = tw[(lane&1)*128 + 8r] (2 addrs)    -> single cmul
    //   s>=7: W = E*C, E = tw[m<<(13-s)] per-lane reg, C broadcast
#pragma unroll
    for (int s = 5; s <= 9; s++) {
        const int L = 1 << (s - 5);
        const bool  up  = (lane & L) != 0;
        const float sgn = up ? -1.f : 1.f;
        float2 E = make_float2(1.f, 0.f);
        if (s >= 7) E = tw[(lane & (L - 1)) << (13 - s)];
#pragma unroll
        for (int r = 0; r < 16; r++) {
            float2 x = reg[r];
            float2 wx;
            if (s == 5)      wx = cmul(x, tw[r << 4]);
            else if (s == 6) wx = cmul(x, tw[((lane & 1) << 7) + (r << 3)]);
            else             wx = cmul(cmul(x, E), tw[(r << 4) >> (s - 5)]);
            float yx = up ? wx.x : x.x;
            float yy = up ? wx.y : x.y;
            float ox = __shfl_xor_sync(0xffffffffu, yx, L);
            float oy = __shfl_xor_sync(0xffffffffu, yy, L);
            reg[r].x = fmaf(sgn, yx, ox);
            reg[r].y = fmaf(sgn, yy, oy);
        }
    }
}

// ---------------------------------------------------------------------------
// Pass 1: row FFTs (2 real rows packed per complex FFT) + transposed store.
// 8 warps/block = 16 rows. grid = 48 slices * 32 groups = 1536.
// Blocks 0..17 also zero the accumulators (done before pass 2 launches).
__global__ void __launch_bounds__(256) kfft_rows(const float* __restrict__ pred,
                                                 const float* __restrict__ tgt) {
    extern __shared__ float2 dsm[];
    float2* sbuf  = dsm;              // 8 * 512
    float2* ttile = dsm + 4096;       // 257 * 17 (padded)
    float2* tw    = ttile + NK * 17;  // 256
    const int REV4[16] = {0,8,4,12,2,10,6,14,1,9,5,13,3,11,7,15};

    int tid = threadIdx.x;
    int bid = blockIdx.x;

    if (bid < 18) {   // folded accumulator zeroing
        for (int i = bid * 256 + tid; i < NIMG * NBINS; i += 18 * 256) {
            ((float*)g_Smag)[i] = 0.0f;
            ((float*)g_Sd)[i]   = 0.0f;
        }
        if (bid == 0) {
            for (int i = tid; i < NBINS; i += 256) g_cnt[i] = 0.0f;
            if (tid == 0) { g_acc = 0.0; g_done = 0u; }
        }
    }
    {
        float sn, cs;
        sincospif(-(float)tid / 256.0f, &sn, &cs);
        tw[tid] = make_float2(cs, sn);
    }

    int slice = bid >> 5;
    int pg    = bid & 31;
    int tens  = (slice >= NIMG) ? 1 : 0;
    int img   = tens ? slice - NIMG : slice;
    const float* src = tens ? tgt : pred;

    int w = tid >> 5, lane = tid & 31;
    int y0 = pg * 16;
    const float* rowA = src + ((size_t)img << 18) + ((size_t)(y0 + 2 * w) << 9);
    const float* rowB = rowA + HH;
    int lr = rev5(lane);

    float2 reg[16];
#pragma unroll
    for (int r = 0; r < 16; r++) {
        int s = REV4[r] * 32 + lr;
        reg[r] = make_float2(rowA[s], rowB[s]);
    }
    __syncthreads();                 // tw ready

    rfft512(reg, lane, tw);

#pragma unroll
    for (int r = 0; r < 16; r++) {
        int t = lane * 16 + r;
        sbuf[(w << 9) + SWZ(t)] = reg[r];
    }
    __syncwarp();

    // Hermitian unpack -> transposed smem tile
    for (int k = lane; k <= 256; k += 32) {
        int m = (512 - k) & 511;
        float2 Z1 = sbuf[(w << 9) + SWZ(k)];
        float2 Z2 = sbuf[(w << 9) + SWZ(m)];
        ttile[k * 17 + 2 * w]     = make_float2(0.5f * (Z1.x + Z2.x), 0.5f * (Z1.y - Z2.y));
        ttile[k * 17 + 2 * w + 1] = make_float2(0.5f * (Z1.y + Z2.y), 0.5f * (Z2.x - Z1.x));
    }
    __syncthreads();

    // coalesced transposed store: 16 consecutive y per k = 128B lines
    float2* outp = g_fftT[tens][img];
    for (int i = tid; i < NK * 16; i += 256) {
        int k = i >> 4, y = i & 15;
        outp[k * 512 + y0 + y] = ttile[k * 17 + y];
    }
}

// ---------------------------------------------------------------------------
// Pass 2: column register FFTs for kx = 0..256, direct global loads,
// run-aggregated bin atomics. 1 warp = 1 column. grid = 24*33.
__global__ void __launch_bounds__(256) kfft_cols() {
    __shared__ float2 tw[256];
    __shared__ float  sbm[NBINS], sbd[NBINS], scn[NBINS];
    const int REV4[16] = {0,8,4,12,2,10,6,14,1,9,5,13,3,11,7,15};

    int tid = threadIdx.x;
    {
        float sn, cs;
        sincospif(-(float)tid / 256.0f, &sn, &cs);
        tw[tid] = make_float2(cs, sn);
    }
    for (int i = tid; i < NBINS; i += 256) { sbm[i] = 0.0f; sbd[i] = 0.0f; scn[i] = 0.0f; }
    __syncthreads();

    int bid = blockIdx.x;
    int img = bid / 33;
    int c0  = (bid % 33) << 3;
    bool docnt = (img == 0);

    int w = tid >> 5, lane = tid & 31;
    int c = c0 + w;

    if (c <= 256) {
        const float2* colP = &g_fftT[0][img][(size_t)c * 512];
        const float2* colT = &g_fftT[1][img][(size_t)c * 512];
        int lr = rev5(lane);

        float2 reg[16];
        // target first: keep only |T|^2
#pragma unroll
        for (int r = 0; r < 16; r++) reg[r] = colT[REV4[r] * 32 + lr];
        rfft512(reg, lane, tw);
        float t2[16];
#pragma unroll
        for (int r = 0; r < 16; r++) t2[r] = reg[r].x * reg[r].x + reg[r].y * reg[r].y;

        // pred
#pragma unroll
        for (int r = 0; r < 16; r++) reg[r] = colP[REV4[r] * 32 + lr];
        rfft512(reg, lane, tw);

        bool dup = (c >= 1 && c <= 255);
        float sx   = (float)((c + 256) & 511) - 255.5f;
        float sxm  = 0.5f - (float)c;
        float sx2  = sx * sx;
        float sxm2 = sxm * sxm;

        // run-aggregated binning: bins monotone in r within a thread
        int   pb1 = -1, pb2 = -1;
        float am1 = 0.f, ad1 = 0.f, cn1 = 0.f;
        float am2 = 0.f, ad2 = 0.f, cn2 = 0.f;
#pragma unroll
        for (int r = 0; r < 16; r++) {
            int ky = lane * 16 + r;
            float2 P = reg[r];
            float p2 = P.x * P.x + P.y * P.y;
            float re = P.x + 1e-8f;
            float mag = 10.0f * __logf(re * re + P.y * P.y);  // 20*ln|re+eps+i*im|
            float df = p2 - t2[r];
            float d  = df * df;

            float sy = (float)((ky + 256) & 511) - 255.5f;
            int b1 = (int)sqrtf(sx2 + sy * sy);
            if (b1 != pb1) {
                if (pb1 >= 0) {
                    atomicAdd(sbm + pb1, am1);
                    atomicAdd(sbd + pb1, ad1);
                    if (docnt) atomicAdd(scn + pb1, cn1);
                }
                pb1 = b1; am1 = 0.f; ad1 = 0.f; cn1 = 0.f;
            }
            am1 += mag; ad1 += d; cn1 += 1.f;

            if (dup) {   // conjugate-mirror pixel: same mag/d, mirrored bin
                int   ky2 = (512 - ky) & 511;
                float sy2 = (float)((ky2 + 256) & 511) - 255.5f;
                int b2 = (int)sqrtf(sxm2 + sy2 * sy2);
                if (b2 != pb2) {
                    if (pb2 >= 0) {
                        atomicAdd(sbm + pb2, am2);
                        atomicAdd(sbd + pb2, ad2);
                        if (docnt) atomicAdd(scn + pb2, cn2);
                    }
                    pb2 = b2; am2 = 0.f; ad2 = 0.f; cn2 = 0.f;
                }
                am2 += mag; ad2 += d; cn2 += 1.f;
            }
        }
        if (pb1 >= 0) {
            atomicAdd(sbm + pb1, am1);
            atomicAdd(sbd + pb1, ad1);
            if (docnt) atomicAdd(scn + pb1, cn1);
        }
        if (pb2 >= 0) {
            atomicAdd(sbm + pb2, am2);
            atomicAdd(sbd + pb2, ad2);
            if (docnt) atomicAdd(scn + pb2, cn2);
        }
    }
    __syncthreads();

    for (int i = tid; i < NBINS; i += 256) {
        atomicAdd(&g_Smag[img][i], sbm[i]);
        atomicAdd(&g_Sd[img][i],   sbd[i]);
        if (docnt) atomicAdd(&g_cnt[i], scn[i]);
    }
}

// ---------------------------------------------------------------------------
// Pass 3: per-image normalize + weighted dot + fused cross-image reduction.
// One block per image; the last block to finish writes the output.
__global__ void __launch_bounds__(512) kimg(float* __restrict__ out) {
    __shared__ float bm[NBINS];
    __shared__ float rmn[512], rmx[512];
    __shared__ double racc[512];

    int tid = threadIdx.x;
    int img = blockIdx.x;

    if (tid < NBINS) bm[tid] = g_Smag[img][tid] / g_cnt[tid];
    __syncthreads();

    float mn = CUDART_INF_F, mx = -CUDART_INF_F;
    if (tid >= 1 && tid <= 360) { mn = bm[tid]; mx = bm[tid]; }
    rmn[tid] = mn; rmx[tid] = mx;
    __syncthreads();
    for (int off = 256; off > 0; off >>= 1) {
        if (tid < off) {
            rmn[tid] = fminf(rmn[tid], rmn[tid + off]);
            rmx[tid] = fmaxf(rmx[tid], rmx[tid + off]);
        }
        __syncthreads();
    }
    float fmn = rmn[0], fmx = rmx[0];

    double acc = 0.0;
    if (tid < NBINS) {
        float psdext;
        if (tid == 361) {
            psdext = 0.0f;
        } else {
            int bb = (tid == 0) ? 1 : tid;       // psd_ext[0] == psd_ext[1]
            psdext = (bm[bb] - fmn) / (fmx - fmn);
        }
        float wv = 1.0f - psdext;
        if (!(wv == wv)) wv = 0.0f;              // nan -> 0
        wv = fminf(fmaxf(wv, 0.0f), 1.0f);       // clip
        acc = (double)wv * (double)g_Sd[img][tid];
    }
    racc[tid] = acc;
    __syncthreads();
    for (int off = 256; off > 0; off >>= 1) {
        if (tid < off) racc[tid] += racc[tid + off];
        __syncthreads();
    }

    if (tid == 0) {
        atomicAdd(&g_acc, racc[0]);
        __threadfence();
        unsigned done = atomicAdd(&g_done, 1u);
        if (done == NIMG - 1) {   // last block: all adds are visible
            double total = atomicAdd(&g_acc, 0.0);
            out[0] = (float)(total / ((double)NIMG * (double)NPIX));
        }
    }
}

// ---------------------------------------------------------------------------
extern "C" void kernel_launch(void* const* d_in, const int* in_sizes, int n_in,
                              void* d_out, int out_size) {
    const float* pred = (const float*)d_in[0];
    const float* tgt  = (const float*)d_in[1];
    float* out = (float*)d_out;

    const int rowSmem = (4096 + NK * 17 + 256) * (int)sizeof(float2);  // ~69.8 KB
    cudaFuncSetAttribute(kfft_rows,
                         cudaFuncAttributeMaxDynamicSharedMemorySize, rowSmem);

    kfft_rows<<<48 * 32, 256, rowSmem>>>(pred, tgt);
    kfft_cols<<<NIMG * 33, 256>>>();
    kimg<<<NIMG, 512>>>(out);
}

// round 10
// speedup vs baseline: 3.7894x; 1.1883x over previous
#include <cuda_runtime.h>
#include <math_constants.h>

#define HH 512
#define WW 512
#define NIMG 24          // 8 * 3 image slices per tensor
#define NBINS 362
#define NPIX (HH * WW)
#define NK 257           // stored spectrum columns 0..256 (Hermitian)

// ---------------------------------------------------------------------------
// Transposed scratch: g_fftT[tens][img][k*512 + y] = row-FFT(row y)[freq k]
__device__ float2 g_fftT[2][NIMG][NK * HH];
__device__ float  g_Smag[NIMG][NBINS];
__device__ float  g_Sd[NIMG][NBINS];
__device__ float  g_cnt[NBINS];
__device__ double g_acc;
__device__ unsigned g_done;

__device__ __forceinline__ int rev5(int x) { return (int)(__brev((unsigned)x) >> 27); }

__device__ __forceinline__ float2 cmul(float2 a, float2 b) {
    return make_float2(a.x * b.x - a.y * b.y, a.x * b.y + a.y * b.x);
}

// Exact floor(sqrt(rsq)) for rsq = integer + 0.5 (exactly representable):
// approx sqrt seed + +/-1 integer fixup.
__device__ __forceinline__ int ibin(float rsq) {
    float ra;
    asm("sqrt.approx.f32 %0, %1;" : "=f"(ra) : "f"(rsq));
    int b = (int)ra;
    float bf = (float)b;
    if ((bf + 1.0f) * (bf + 1.0f) <= rsq) b++;
    else if (bf * bf > rsq) b--;
    return b;
}

// ---------------------------------------------------------------------------
// Fully register-resident 512-pt radix-2 DIT FFT per warp.
// Input: reg[r] = x[rev9(lane*16+r)]. Output: natural order, t = lane*16+r.
// tw[k] = exp(-2*pi*i*k/512), k in [0,256).
__device__ __forceinline__ void rfft512(float2 reg[16], int lane, const float2* tw) {
    const float c16[8] = { 1.f,  0.92387953f,  0.70710678f,  0.38268343f,
                           0.f, -0.38268343f, -0.70710678f, -0.92387953f };
    const float s16[8] = { 0.f, -0.38268343f, -0.70710678f, -0.92387953f,
                          -1.f, -0.92387953f, -0.70710678f, -0.38268343f };
#pragma unroll
    for (int s = 1; s <= 4; s++) {
        const int half = 1 << (s - 1);
#pragma unroll
        for (int b = 0; b < 8; b++) {
            int j  = b & (half - 1);
            int i0 = ((b >> (s - 1)) << s) + j;
            int i1 = i0 + half;
            int ji = j << (4 - s);
            float2 u = reg[i0], v = reg[i1];
            float2 wv = make_float2(v.x * c16[ji] - v.y * s16[ji],
                                    v.x * s16[ji] + v.y * c16[ji]);
            reg[i0] = make_float2(u.x + wv.x, u.y + wv.y);
            reg[i1] = make_float2(u.x - wv.x, u.y - wv.y);
        }
    }
    // stages 5-9: cross-lane, pre-twiddle form
#pragma unroll
    for (int s = 5; s <= 9; s++) {
        const int L = 1 << (s - 5);
        const bool  up  = (lane & L) != 0;
        const float sgn = up ? -1.f : 1.f;
        float2 E = make_float2(1.f, 0.f);
        if (s >= 7) E = tw[(lane & (L - 1)) << (13 - s)];
#pragma unroll
        for (int r = 0; r < 16; r++) {
            float2 x = reg[r];
            float2 wx;
            if (s == 5)      wx = cmul(x, tw[r << 4]);
            else if (s == 6) wx = cmul(x, tw[((lane & 1) << 7) + (r << 3)]);
            else             wx = cmul(cmul(x, E), tw[(r << 4) >> (s - 5)]);
            float yx = up ? wx.x : x.x;
            float yy = up ? wx.y : x.y;
            float ox = __shfl_xor_sync(0xffffffffu, yx, L);
            float oy = __shfl_xor_sync(0xffffffffu, yy, L);
            reg[r].x = fmaf(sgn, yx, ox);
            reg[r].y = fmaf(sgn, yy, oy);
        }
    }
}

// ---------------------------------------------------------------------------
// Pass 1: row FFTs (2 real rows packed per complex FFT), register Hermitian
// unpack via shfl (no staging buffer), transposed store through a swizzled
// smem tile. 8 warps/block = 16 rows. grid = 48 slices * 32 groups.
__global__ void __launch_bounds__(256) kfft_rows(const float* __restrict__ pred,
                                                 const float* __restrict__ tgt) {
    __shared__ float2 ttile[NK * 17];   // [k][y^swz], padded stride 17
    __shared__ float2 tw[256];
    const int REV4[16] = {0,8,4,12,2,10,6,14,1,9,5,13,3,11,7,15};

    int tid = threadIdx.x;
    int bid = blockIdx.x;

    if (bid < 18) {   // folded accumulator zeroing
        for (int i = bid * 256 + tid; i < NIMG * NBINS; i += 18 * 256) {
            ((float*)g_Smag)[i] = 0.0f;
            ((float*)g_Sd)[i]   = 0.0f;
        }
        if (bid == 0) {
            for (int i = tid; i < NBINS; i += 256) g_cnt[i] = 0.0f;
            if (tid == 0) { g_acc = 0.0; g_done = 0u; }
        }
    }
    {
        float sn, cs;
        sincospif(-(float)tid / 256.0f, &sn, &cs);
        tw[tid] = make_float2(cs, sn);
    }

    int slice = bid >> 5;
    int pg    = bid & 31;
    int tens  = (slice >= NIMG) ? 1 : 0;
    int img   = tens ? slice - NIMG : slice;
    const float* src = tens ? tgt : pred;

    int w = tid >> 5, lane = tid & 31;
    int y0 = pg * 16;
    const float* rowA = src + ((size_t)img << 18) + ((size_t)(y0 + 2 * w) << 9);
    const float* rowB = rowA + HH;
    int lr = rev5(lane);

    float2 reg[16];
#pragma unroll
    for (int r = 0; r < 16; r++) {
        int s = REV4[r] * 32 + lr;
        reg[r] = make_float2(rowA[s], rowB[s]);
    }
    __syncthreads();                 // tw ready

    rfft512(reg, lane, tw);

    // Hermitian unpack in registers: Z2 = Z[(512-k)&511]
    //   r=0: partner lane (32-lane)&31, reg 0
    //   r>0: partner lane lane^31,      reg 16-r
    int k0 = lane << 4;
    int sw = lane & 15;
    int yyA = (2 * w) ^ sw, yyB = (2 * w + 1) ^ sw;
    {
        int p0 = (32 - lane) & 31;
        float zx = __shfl_sync(0xffffffffu, reg[0].x, p0);
        float zy = __shfl_sync(0xffffffffu, reg[0].y, p0);
        if (k0 <= 256) {
            float2 Z1 = reg[0];
            ttile[k0 * 17 + yyA] = make_float2(0.5f * (Z1.x + zx), 0.5f * (Z1.y - zy));
            ttile[k0 * 17 + yyB] = make_float2(0.5f * (Z1.y + zy), 0.5f * (zx - Z1.x));
        }
    }
#pragma unroll
    for (int r = 1; r < 16; r++) {
        float zx = __shfl_sync(0xffffffffu, reg[16 - r].x, lane ^ 31);
        float zy = __shfl_sync(0xffffffffu, reg[16 - r].y, lane ^ 31);
        if (lane < 16) {
            int k = k0 + r;
            float2 Z1 = reg[r];
            ttile[k * 17 + yyA] = make_float2(0.5f * (Z1.x + zx), 0.5f * (Z1.y - zy));
            ttile[k * 17 + yyB] = make_float2(0.5f * (Z1.y + zy), 0.5f * (zx - Z1.x));
        }
    }
    __syncthreads();

    // coalesced transposed store: 16 consecutive y per k = 128B lines
    float2* outp = g_fftT[tens][img];
    for (int i = tid; i < NK * 16; i += 256) {
        int k = i >> 4, y = i & 15;
        outp[k * 512 + y0 + y] = ttile[k * 17 + (y ^ ((k >> 4) & 15))];
    }
}

// ---------------------------------------------------------------------------
// Pass 2: column register FFTs for kx = 0..256, direct global loads,
// run-aggregated bin atomics, exact cheap binning. 1 warp = 1 column.
__global__ void __launch_bounds__(256, 3) kfft_cols() {
    __shared__ float2 tw[256];
    __shared__ float  sbm[NBINS], sbd[NBINS], scn[NBINS];
    const int REV4[16] = {0,8,4,12,2,10,6,14,1,9,5,13,3,11,7,15};

    int tid = threadIdx.x;
    {
        float sn, cs;
        sincospif(-(float)tid / 256.0f, &sn, &cs);
        tw[tid] = make_float2(cs, sn);
    }
    for (int i = tid; i < NBINS; i += 256) { sbm[i] = 0.0f; sbd[i] = 0.0f; scn[i] = 0.0f; }
    __syncthreads();

    int bid = blockIdx.x;
    int img = bid / 33;
    int c0  = (bid % 33) << 3;
    bool docnt = (img == 0);

    int w = tid >> 5, lane = tid & 31;
    int c = c0 + w;

    if (c <= 256) {
        const float2* colP = &g_fftT[0][img][(size_t)c * 512];
        const float2* colT = &g_fftT[1][img][(size_t)c * 512];
        int lr = rev5(lane);

        float2 reg[16];
        // target first: keep only |T|^2
#pragma unroll
        for (int r = 0; r < 16; r++) reg[r] = colT[REV4[r] * 32 + lr];
        rfft512(reg, lane, tw);
        float t2[16];
#pragma unroll
        for (int r = 0; r < 16; r++) t2[r] = reg[r].x * reg[r].x + reg[r].y * reg[r].y;

        // pred
#pragma unroll
        for (int r = 0; r < 16; r++) reg[r] = colP[REV4[r] * 32 + lr];
        rfft512(reg, lane, tw);

        bool dup = (c >= 1 && c <= 255);
        float sx   = (float)((c + 256) & 511) - 255.5f;
        float sxm  = 0.5f - (float)c;
        float sx2  = sx * sx;
        float sxm2 = sxm * sxm;

        // run-aggregated binning: bins change slowly within a thread's 16 ky
        int   pb1 = -1, pb2 = -1;
        float am1 = 0.f, ad1 = 0.f, cn1 = 0.f;
        float am2 = 0.f, ad2 = 0.f, cn2 = 0.f;
#pragma unroll
        for (int r = 0; r < 16; r++) {
            int ky = lane * 16 + r;
            float2 P = reg[r];
            float p2 = P.x * P.x + P.y * P.y;
            float re = P.x + 1e-8f;
            float mag = 10.0f * __logf(re * re + P.y * P.y);  // 20*ln|re+eps+i*im|
            float df = p2 - t2[r];
            float d  = df * df;

            float sy = (float)((ky + 256) & 511) - 255.5f;
            int b1 = ibin(sx2 + sy * sy);
            if (b1 != pb1) {
                if (pb1 >= 0) {
                    atomicAdd(sbm + pb1, am1);
                    atomicAdd(sbd + pb1, ad1);
                    if (docnt) atomicAdd(scn + pb1, cn1);
                }
                pb1 = b1; am1 = 0.f; ad1 = 0.f; cn1 = 0.f;
            }
            am1 += mag; ad1 += d; cn1 += 1.f;

            if (dup) {   // conjugate-mirror pixel: same mag/d, mirrored bin
                int   ky2 = (512 - ky) & 511;
                float sy2 = (float)((ky2 + 256) & 511) - 255.5f;
                int b2 = ibin(sxm2 + sy2 * sy2);
                if (b2 != pb2) {
                    if (pb2 >= 0) {
                        atomicAdd(sbm + pb2, am2);
                        atomicAdd(sbd + pb2, ad2);
                        if (docnt) atomicAdd(scn + pb2, cn2);
                    }
                    pb2 = b2; am2 = 0.f; ad2 = 0.f; cn2 = 0.f;
                }
                am2 += mag; ad2 += d; cn2 += 1.f;
            }
        }
        if (pb1 >= 0) {
            atomicAdd(sbm + pb1, am1);
            atomicAdd(sbd + pb1, ad1);
            if (docnt) atomicAdd(scn + pb1, cn1);
        }
        if (pb2 >= 0) {
            atomicAdd(sbm + pb2, am2);
            atomicAdd(sbd + pb2, ad2);
            if (docnt) atomicAdd(scn + pb2, cn2);
        }
    }
    __syncthreads();

    for (int i = tid; i < NBINS; i += 256) {
        atomicAdd(&g_Smag[img][i], sbm[i]);
        atomicAdd(&g_Sd[img][i],   sbd[i]);
        if (docnt) atomicAdd(&g_cnt[i], scn[i]);
    }
}

// ---------------------------------------------------------------------------
// Pass 3: one WARP per image — shuffle-only normalize + weighted dot,
// fused cross-image reduction; last block writes the output.
__global__ void __launch_bounds__(32) kimg(float* __restrict__ out) {
    int img  = blockIdx.x;
    int lane = threadIdx.x;

    float bm[12];
    float mn = CUDART_INF_F, mx = -CUDART_INF_F;
#pragma unroll
    for (int i = 0; i < 12; i++) {
        int b = lane + (i << 5);
        float v = 0.0f;
        if (b < NBINS) v = g_Smag[img][b] / g_cnt[b];
        bm[i] = v;
        if (b >= 1 && b <= 360) { mn = fminf(mn, v); mx = fmaxf(mx, v); }
    }
#pragma unroll
    for (int o = 16; o > 0; o >>= 1) {
        mn = fminf(mn, __shfl_xor_sync(0xffffffffu, mn, o));
        mx = fmaxf(mx, __shfl_xor_sync(0xffffffffu, mx, o));
    }
    float bm1 = __shfl_sync(0xffffffffu, bm[0], 1);   // bin-1 mean (for bin 0)

    double acc = 0.0;
#pragma unroll
    for (int i = 0; i < 12; i++) {
        int b = lane + (i << 5);
        if (b < NBINS) {
            float psdext;
            if (b == 361)    psdext = 0.0f;
            else {
                float base = (b == 0) ? bm1 : bm[i];  // psd_ext[0] == psd_ext[1]
                psdext = (base - mn) / (mx - mn);
            }
            float wv = 1.0f - psdext;
            if (!(wv == wv)) wv = 0.0f;               // nan -> 0
            wv = fminf(fmaxf(wv, 0.0f), 1.0f);        // clip
            acc += (double)wv * (double)g_Sd[img][b];
        }
    }
#pragma unroll
    for (int o = 16; o > 0; o >>= 1)
        acc += __shfl_xor_sync(0xffffffffu, acc, o);

    if (lane == 0) {
        atomicAdd(&g_acc, acc);
        __threadfence();
        unsigned done = atomicAdd(&g_done, 1u);
        if (done == NIMG - 1) {
            double total = atomicAdd(&g_acc, 0.0);
            out[0] = (float)(total / ((double)NIMG * (double)NPIX));
        }
    }
}

// ---------------------------------------------------------------------------
extern "C" void kernel_launch(void* const* d_in, const int* in_sizes, int n_in,
                              void* d_out, int out_size) {
    const float* pred = (const float*)d_in[0];
    const float* tgt  = (const float*)d_in[1];
    float* out = (float*)d_out;

    kfft_rows<<<48 * 32, 256>>>(pred, tgt);
    kfft_cols<<<NIMG * 33, 256>>>();
    kimg<<<NIMG, 32>>>(out);
}